// round 15
// baseline (speedup 1.0000x reference)
#include <cuda_runtime.h>
#include <cuda_fp16.h>
#include <mma.h>
#include <math.h>
#include <stdint.h>

using namespace nvcuda;

#define Bn 4
#define Tn 2048
#define Dn 1024
#define Hn 16
#define HDn 64
#define MROWS (Bn*Tn)      // 8192
#define QKVN (3*Dn)        // 3072

__device__ __half g_qkvh[(size_t)MROWS * QKVN];
__device__ __half g_atth[(size_t)MROWS * Dn];
__device__ __half g_xh[(size_t)MROWS * Dn];
__device__ __half g_wqh[(size_t)Dn * QKVN];
__device__ __half g_woh[(size_t)Dn * Dn];

__device__ __forceinline__ uint32_t s2u(const void* p) {
    return (uint32_t)__cvta_generic_to_shared(p);
}
__device__ __forceinline__ void cp16(uint32_t dst, const void* src) {
    asm volatile("cp.async.cg.shared.global [%0], [%1], 16;" :: "r"(dst), "l"(src));
}
__device__ __forceinline__ void cp_commit() { asm volatile("cp.async.commit_group;"); }
__device__ __forceinline__ void cp_wait0()  { asm volatile("cp.async.wait_group 0;"); }

// exp(x) for |x| <= 0.125: degree-4 Taylor, max rel err ~2.5e-7. FMA pipe only.
__device__ __forceinline__ float exp_small(float x) {
    float p = fmaf(x, 1.f/24.f, 1.f/6.f);
    p = fmaf(x, p, 0.5f);
    p = fmaf(x, p, 1.f);
    return fmaf(x, p, 1.f);
}

__global__ void __launch_bounds__(256) f2h_kernel(
    const float* __restrict__ src, __half* __restrict__ dst, int total4)
{
    int idx = blockIdx.x * blockDim.x + threadIdx.x;
    if (idx >= total4) return;
    float4 v = *(const float4*)&src[idx * 4];
    *(__half2*)&dst[idx*4]   = __floats2half2_rn(v.x, v.y);
    *(__half2*)&dst[idx*4+2] = __floats2half2_rn(v.z, v.w);
}

// ---------------------------------------------------------------------------
// FP16 GEMM: 128x128 tile, BK=64, warp tile 64x32, cp.async double buffer.
// Staged epilogue modes:
//   MODE 0: fp32 out + bias (out-proj)
//   MODE 2: half out; q/k column tiles get fused RoPE + L2 norm (q also
//           pre-scaled 1/8); v tiles plain convert. (GEMM1)
// ---------------------------------------------------------------------------
#define AP_A 72
#define AP_B 136
#define A_STG (128*AP_A)
#define B_STG (64*AP_B)
#define GEMM_SMEM ((2*A_STG + 2*B_STG) * 2)
#define SP 132

template <int MODE>
__global__ void __launch_bounds__(256, 2) gemm_h(
    const __half* __restrict__ A, const __half* __restrict__ Bm,
    const float* __restrict__ bias,
    __half* __restrict__ Ch, float* __restrict__ Cf,
    int M, int N, int K)
{
    extern __shared__ __half smh[];
    __half* As = smh;
    __half* Bs = smh + 2*A_STG;

    const int tid = threadIdx.x;
    const int bm = blockIdx.y * 128;
    const int bn = blockIdx.x * 128;
    const int w  = tid >> 5;
    const int wm = (w >> 2) * 64;
    const int wn = (w & 3) * 32;

    wmma::fragment<wmma::accumulator, 16, 16, 16, float> acc[4][2];
    #pragma unroll
    for (int i = 0; i < 4; i++)
        #pragma unroll
        for (int j = 0; j < 2; j++) wmma::fill_fragment(acc[i][j], 0.f);

    const int nk = K / 64;

    auto prefetch = [&](int kt, int stg) {
        const int k0 = kt * 64;
        __half* ad = As + stg * A_STG;
        __half* bd = Bs + stg * B_STG;
        #pragma unroll
        for (int i = 0; i < 4; i++) {
            int id = tid + 256*i;
            int r = id >> 3, c = (id & 7) * 8;
            cp16(s2u(ad + r*AP_A + c), &A[(size_t)(bm + r) * K + k0 + c]);
        }
        #pragma unroll
        for (int i = 0; i < 4; i++) {
            int id = tid + 256*i;
            int r = id >> 4, c = (id & 15) * 8;
            cp16(s2u(bd + r*AP_B + c), &Bm[(size_t)(k0 + r) * N + bn + c]);
        }
        cp_commit();
    };

    prefetch(0, 0);
    int stg = 0;

    for (int kt = 0; kt < nk; kt++) {
        cp_wait0();
        __syncthreads();
        if (kt + 1 < nk) prefetch(kt + 1, stg ^ 1);

        const __half* a0 = As + stg * A_STG;
        const __half* b0 = Bs + stg * B_STG;
        #pragma unroll
        for (int kk = 0; kk < 4; kk++) {
            wmma::fragment<wmma::matrix_a, 16, 16, 16, __half, wmma::row_major> af[4];
            wmma::fragment<wmma::matrix_b, 16, 16, 16, __half, wmma::row_major> bf[2];
            #pragma unroll
            for (int i = 0; i < 4; i++)
                wmma::load_matrix_sync(af[i], a0 + (wm + i*16)*AP_A + kk*16, AP_A);
            #pragma unroll
            for (int j = 0; j < 2; j++)
                wmma::load_matrix_sync(bf[j], b0 + (kk*16)*AP_B + wn + j*16, AP_B);
            #pragma unroll
            for (int i = 0; i < 4; i++)
                #pragma unroll
                for (int j = 0; j < 2; j++)
                    wmma::mma_sync(acc[i][j], af[i], bf[j], acc[i][j]);
        }
        stg ^= 1;
    }

    __syncthreads();
    float* stage = reinterpret_cast<float*>(smh);
    #pragma unroll
    for (int i = 0; i < 4; i++)
        #pragma unroll
        for (int j = 0; j < 2; j++)
            wmma::store_matrix_sync(stage + (wm + i*16)*SP + wn + j*16,
                                    acc[i][j], SP, wmma::mem_row_major);
    __syncthreads();

    if (MODE == 0) {
        #pragma unroll
        for (int it = 0; it < 8; it++) {
            int idx = tid + 256*it;
            int r = idx >> 4;
            int c = (idx & 15) * 8;
            const float* srow = stage + r*SP + c;
            float* dst = Cf + (size_t)(bm + r) * N + bn + c;
            float4 v0 = *(const float4*)(srow);
            float4 v1 = *(const float4*)(srow + 4);
            const float* bp = bias + bn + c;
            v0.x += bp[0]; v0.y += bp[1]; v0.z += bp[2]; v0.w += bp[3];
            v1.x += bp[4]; v1.y += bp[5]; v1.z += bp[6]; v1.w += bp[7];
            *(float4*)(dst)     = v0;
            *(float4*)(dst + 4) = v1;
        }
    } else {
        const int which = bn >> 10;            // 0=q, 1=k, 2=v
        if (which < 2) {
            // Fused RoPE + L2 norm: thread -> (row, head) pair
            const int r  = tid >> 1;
            const int hc = (tid & 1) * 64;
            float* srow = stage + r*SP + hc;
            const int t = (bm + r) & (Tn - 1);

            float ss = 0.f;
            #pragma unroll
            for (int j = 0; j < 32; j++) {
                const float inv_freq = exp2f(-(float)j * (13.287712379549449f / 32.f));
                float s, c;
                sincosf((float)t * inv_freq, &s, &c);
                const float x1 = srow[j];
                const float x2 = srow[j + 32];
                const float r1 = x1*c - x2*s;
                const float r2 = x1*s + x2*c;
                ss += r1*r1 + r2*r2;
                srow[j]      = r1;
                srow[j + 32] = r2;
            }
            float inv = rsqrtf(ss + 1e-6f);
            if (which == 0) inv *= 0.125f;     // fold 1/sqrt(HD) into q

            __half* dst = Ch + (size_t)(bm + r) * N + bn + hc;
            #pragma unroll
            for (int j = 0; j < 64; j += 2)
                *(__half2*)(dst + j) =
                    __floats2half2_rn(srow[j] * inv, srow[j+1] * inv);
        } else {
            #pragma unroll
            for (int it = 0; it < 8; it++) {
                int idx = tid + 256*it;
                int r = idx >> 4;
                int c = (idx & 15) * 8;
                const float* srow = stage + r*SP + c;
                __half* dst = Ch + (size_t)(bm + r) * N + bn + c;
                #pragma unroll
                for (int k = 0; k < 4; k++)
                    *(__half2*)(dst + 2*k) = __floats2half2_rn(srow[2*k], srow[2*k+1]);
            }
        }
    }
}

// ---------------------------------------------------------------------------
// FP16 flash attention (R14 config): 128 q-rows / 256 threads / 8 warps,
// half S accumulator, polynomial exp (|S|<=0.125), 3 blocks/SM.
// ---------------------------------------------------------------------------
#define APH 72
#define OXP 68
#define KV_STGH (64*APH)
#define SM_Q   0
#define SM_K   (SM_Q + 128*APH)
#define SM_V   (SM_K + 2*KV_STGH)
#define SM_P   (SM_V + 2*KV_STGH)
#define SM_HALVES (SM_P + 128*APH)
#define ATT_SMEM (SM_HALVES*2 + 128*4)

__global__ void __launch_bounds__(256) attn_h_kernel(
    const __half* __restrict__ qkvh, __half* __restrict__ outp)
{
    extern __shared__ __half smh[];
    __half* Qs = smh + SM_Q;
    __half* Ks = smh + SM_K;
    __half* Vs = smh + SM_V;
    __half* Ph = smh + SM_P;
    float* lrow = (float*)(smh + SM_HALVES);
    float* Ostage = (float*)(smh + SM_K);

    const int tid  = threadIdx.x;
    const int w    = tid >> 5;
    const int lane = tid & 31;

    const int qt = blockIdx.x & 15;
    const int h  = (blockIdx.x >> 4) & (Hn-1);
    const int b  = blockIdx.x >> 8;
    const int q0 = qt * 128;

    const __half* qbase = qkvh + (size_t)(b*Tn) * QKVN + h*HDn;
    const __half* kbase = qbase + Dn;
    const __half* vbase = qbase + 2*Dn;

    auto prefetch_kv = [&](int kt, int stg) {
        __half* kd = Ks + stg*KV_STGH;
        __half* vd = Vs + stg*KV_STGH;
        #pragma unroll
        for (int i = 0; i < 2; i++) {
            int id = tid + 256*i;
            int r = id >> 3, c = (id & 7) * 8;
            cp16(s2u(kd + r*APH + c), kbase + (size_t)(kt*64 + r) * QKVN + c);
        }
        #pragma unroll
        for (int i = 0; i < 2; i++) {
            int id = tid + 256*i;
            int r = id >> 3, c = (id & 7) * 8;
            cp16(s2u(vd + r*APH + c), vbase + (size_t)(kt*64 + r) * QKVN + c);
        }
        cp_commit();
    };

    #pragma unroll
    for (int i = 0; i < 4; i++) {
        int id = tid + 256*i;
        int r = id >> 3, c = (id & 7) * 8;
        cp16(s2u(Qs + r*APH + c), qbase + (size_t)(q0 + r) * QKVN + c);
    }
    cp_commit();
    prefetch_kv(0, 0);

    if (tid < 128) lrow[tid] = 0.f;

    wmma::fragment<wmma::accumulator, 16, 16, 16, float> oacc[4];
    #pragma unroll
    for (int j = 0; j < 4; j++) wmma::fill_fragment(oacc[j], 0.f);

    const int rowm = w * 16;
    int stg = 0;

    for (int kt = 0; kt < Tn/64; kt++) {
        cp_wait0();
        __syncthreads();
        if (kt + 1 < Tn/64) prefetch_kv(kt + 1, stg ^ 1);

        const __half* kc = Ks + stg*KV_STGH;
        const __half* vc = Vs + stg*KV_STGH;

        // S = Q @ K^T, half accumulator
        wmma::fragment<wmma::accumulator, 16, 16, 16, __half> sacc[4];
        #pragma unroll
        for (int j = 0; j < 4; j++) wmma::fill_fragment(sacc[j], __float2half(0.f));
        #pragma unroll
        for (int ks = 0; ks < 4; ks++) {
            wmma::fragment<wmma::matrix_a, 16, 16, 16, __half, wmma::row_major> aq;
            wmma::load_matrix_sync(aq, Qs + rowm*APH + ks*16, APH);
            #pragma unroll
            for (int j = 0; j < 4; j++) {
                wmma::fragment<wmma::matrix_b, 16, 16, 16, __half, wmma::col_major> bk;
                wmma::load_matrix_sync(bk, kc + j*16*APH + ks*16, APH);
                wmma::mma_sync(sacc[j], aq, bk, sacc[j]);
            }
        }
        #pragma unroll
        for (int j = 0; j < 4; j++)
            wmma::store_matrix_sync(Ph + rowm*APH + j*16, sacc[j], APH, wmma::mem_row_major);
        __syncwarp();

        // P = half(exp(S)) in place, polynomial exp; row sums of rounded P.
        {
            const int rr = rowm + (lane >> 1);
            const int cc = (lane & 1) * 32;
            __half* pr = Ph + rr*APH + cc;
            float sum = 0.f;
            #pragma unroll
            for (int j = 0; j < 32; j += 2) {
                __half2 sv = *(__half2*)(pr + j);
                float e0 = exp_small(__half2float(__low2half(sv)));
                float e1 = exp_small(__half2float(__high2half(sv)));
                __half2 hp = __floats2half2_rn(e0, e1);
                *(__half2*)(pr + j) = hp;
                sum += __half2float(__low2half(hp)) + __half2float(__high2half(hp));
            }
            sum += __shfl_xor_sync(0xffffffffu, sum, 1);
            if (!(lane & 1)) lrow[rr] += sum;
        }
        __syncwarp();

        // O += P @ V
        #pragma unroll
        for (int ks = 0; ks < 4; ks++) {
            wmma::fragment<wmma::matrix_a, 16, 16, 16, __half, wmma::row_major> ap;
            wmma::load_matrix_sync(ap, Ph + rowm*APH + ks*16, APH);
            #pragma unroll
            for (int j = 0; j < 4; j++) {
                wmma::fragment<wmma::matrix_b, 16, 16, 16, __half, wmma::row_major> bv;
                wmma::load_matrix_sync(bv, vc + ks*16*APH + j*16, APH);
                wmma::mma_sync(oacc[j], ap, bv, oacc[j]);
            }
        }
        stg ^= 1;
    }

    __syncthreads();
    #pragma unroll
    for (int j = 0; j < 4; j++)
        wmma::store_matrix_sync(Ostage + rowm*OXP + j*16, oacc[j], OXP, wmma::mem_row_major);
    __syncthreads();

    {
        const int r  = tid >> 1;
        const int c0 = (tid & 1) * 32;
        const float inv = 1.f / lrow[r];
        const float* srcr = Ostage + r*OXP + c0;
        __half* dst = outp + (size_t)(b*Tn + q0 + r) * Dn + h*HDn + c0;
        #pragma unroll
        for (int j = 0; j < 32; j += 2)
            *(__half2*)(dst + j) = __floats2half2_rn(srcr[j] * inv, srcr[j+1] * inv);
    }
}

// ---------------------------------------------------------------------------
extern "C" void kernel_launch(void* const* d_in, const int* in_sizes, int n_in,
                              void* d_out, int out_size)
{
    const float* x    = (const float*)d_in[0];
    const float* Wqkv = (const float*)d_in[1];
    const float* Wo   = (const float*)d_in[2];
    const float* bo   = (const float*)d_in[3];
    float* out = (float*)d_out;

    __half *qkvh, *atth, *xh, *wqh, *woh;
    cudaGetSymbolAddress((void**)&qkvh, g_qkvh);
    cudaGetSymbolAddress((void**)&atth, g_atth);
    cudaGetSymbolAddress((void**)&xh,   g_xh);
    cudaGetSymbolAddress((void**)&wqh,  g_wqh);
    cudaGetSymbolAddress((void**)&woh,  g_woh);

    cudaFuncSetAttribute((const void*)gemm_h<2>,
                         cudaFuncAttributeMaxDynamicSharedMemorySize, GEMM_SMEM);
    cudaFuncSetAttribute((const void*)gemm_h<0>,
                         cudaFuncAttributeMaxDynamicSharedMemorySize, GEMM_SMEM);
    cudaFuncSetAttribute(attn_h_kernel,
                         cudaFuncAttributeMaxDynamicSharedMemorySize, ATT_SMEM);

    // 0) fp16 conversions of inputs
    {
        int n4;
        n4 = MROWS*Dn/4;  f2h_kernel<<<(n4+255)/256, 256>>>(x,    xh,  n4);
        n4 = Dn*QKVN/4;   f2h_kernel<<<(n4+255)/256, 256>>>(Wqkv, wqh, n4);
        n4 = Dn*Dn/4;     f2h_kernel<<<(n4+255)/256, 256>>>(Wo,   woh, n4);
    }
    // 1) qkvh = rope_norm(xh @ wqh)   (RoPE/norm fused into epilogue)
    {
        dim3 grid(QKVN/128, MROWS/128);
        gemm_h<2><<<grid, 256, GEMM_SMEM>>>(xh, wqh, nullptr, qkvh, nullptr,
                                            MROWS, QKVN, Dn);
    }
    // 2) attention
    {
        dim3 grid(Bn * Hn * (Tn/128));   // 1024
        attn_h_kernel<<<grid, 256, ATT_SMEM>>>(qkvh, atth);
    }
    // 3) out(fp32) = atth @ woh + bo
    {
        dim3 grid(Dn/128, MROWS/128);
        gemm_h<0><<<grid, 256, GEMM_SMEM>>>(atth, woh, bo, nullptr, out,
                                            MROWS, Dn, Dn);
    }
}

// round 16
// speedup vs baseline: 1.0286x; 1.0286x over previous
#include <cuda_runtime.h>
#include <cuda_fp16.h>
#include <mma.h>
#include <math.h>
#include <stdint.h>

using namespace nvcuda;

#define Bn 4
#define Tn 2048
#define Dn 1024
#define Hn 16
#define HDn 64
#define MROWS (Bn*Tn)      // 8192
#define QKVN (3*Dn)        // 3072

__device__ __half g_qkvh[(size_t)MROWS * QKVN];
__device__ __half g_atth[(size_t)MROWS * Dn];
__device__ __half g_xh[(size_t)MROWS * Dn];
__device__ __half g_wqh[(size_t)Dn * QKVN];
__device__ __half g_woh[(size_t)Dn * Dn];

__device__ __forceinline__ uint32_t s2u(const void* p) {
    return (uint32_t)__cvta_generic_to_shared(p);
}
__device__ __forceinline__ void cp16(uint32_t dst, const void* src) {
    asm volatile("cp.async.cg.shared.global [%0], [%1], 16;" :: "r"(dst), "l"(src));
}
__device__ __forceinline__ void cp_commit() { asm volatile("cp.async.commit_group;"); }
__device__ __forceinline__ void cp_wait0()  { asm volatile("cp.async.wait_group 0;"); }

// exp(x) for |x| <= 0.125: degree-4 Taylor, max rel err ~2.5e-7. FMA pipe only.
__device__ __forceinline__ float exp_small(float x) {
    float p = fmaf(x, 1.f/24.f, 1.f/6.f);
    p = fmaf(x, p, 0.5f);
    p = fmaf(x, p, 1.f);
    return fmaf(x, p, 1.f);
}

__global__ void __launch_bounds__(256) f2h_kernel(
    const float* __restrict__ src, __half* __restrict__ dst, int total4)
{
    int idx = blockIdx.x * blockDim.x + threadIdx.x;
    if (idx >= total4) return;
    float4 v = *(const float4*)&src[idx * 4];
    *(__half2*)&dst[idx*4]   = __floats2half2_rn(v.x, v.y);
    *(__half2*)&dst[idx*4+2] = __floats2half2_rn(v.z, v.w);
}

// ---------------------------------------------------------------------------
// FP16 GEMM (R13/R14 config): 128x128 tile, BK=64, warp tile 64x32,
// cp.async double buffer; staged epilogue (OUT_HALF or fp32+bias).
// ---------------------------------------------------------------------------
#define AP_A 72
#define AP_B 136
#define A_STG (128*AP_A)
#define B_STG (64*AP_B)
#define GEMM_SMEM ((2*A_STG + 2*B_STG) * 2)
#define SP 132

template <int OUT_HALF, int WITH_BIAS>
__global__ void __launch_bounds__(256, 2) gemm_h(
    const __half* __restrict__ A, const __half* __restrict__ Bm,
    const float* __restrict__ bias,
    __half* __restrict__ Ch, float* __restrict__ Cf,
    int M, int N, int K)
{
    extern __shared__ __half smh[];
    __half* As = smh;
    __half* Bs = smh + 2*A_STG;

    const int tid = threadIdx.x;
    const int bm = blockIdx.y * 128;
    const int bn = blockIdx.x * 128;
    const int w  = tid >> 5;
    const int wm = (w >> 2) * 64;
    const int wn = (w & 3) * 32;

    wmma::fragment<wmma::accumulator, 16, 16, 16, float> acc[4][2];
    #pragma unroll
    for (int i = 0; i < 4; i++)
        #pragma unroll
        for (int j = 0; j < 2; j++) wmma::fill_fragment(acc[i][j], 0.f);

    const int nk = K / 64;

    auto prefetch = [&](int kt, int stg) {
        const int k0 = kt * 64;
        __half* ad = As + stg * A_STG;
        __half* bd = Bs + stg * B_STG;
        #pragma unroll
        for (int i = 0; i < 4; i++) {
            int id = tid + 256*i;
            int r = id >> 3, c = (id & 7) * 8;
            cp16(s2u(ad + r*AP_A + c), &A[(size_t)(bm + r) * K + k0 + c]);
        }
        #pragma unroll
        for (int i = 0; i < 4; i++) {
            int id = tid + 256*i;
            int r = id >> 4, c = (id & 15) * 8;
            cp16(s2u(bd + r*AP_B + c), &Bm[(size_t)(k0 + r) * N + bn + c]);
        }
        cp_commit();
    };

    prefetch(0, 0);
    int stg = 0;

    for (int kt = 0; kt < nk; kt++) {
        cp_wait0();
        __syncthreads();
        if (kt + 1 < nk) prefetch(kt + 1, stg ^ 1);

        const __half* a0 = As + stg * A_STG;
        const __half* b0 = Bs + stg * B_STG;
        #pragma unroll
        for (int kk = 0; kk < 4; kk++) {
            wmma::fragment<wmma::matrix_a, 16, 16, 16, __half, wmma::row_major> af[4];
            wmma::fragment<wmma::matrix_b, 16, 16, 16, __half, wmma::row_major> bf[2];
            #pragma unroll
            for (int i = 0; i < 4; i++)
                wmma::load_matrix_sync(af[i], a0 + (wm + i*16)*AP_A + kk*16, AP_A);
            #pragma unroll
            for (int j = 0; j < 2; j++)
                wmma::load_matrix_sync(bf[j], b0 + (kk*16)*AP_B + wn + j*16, AP_B);
            #pragma unroll
            for (int i = 0; i < 4; i++)
                #pragma unroll
                for (int j = 0; j < 2; j++)
                    wmma::mma_sync(acc[i][j], af[i], bf[j], acc[i][j]);
        }
        stg ^= 1;
    }

    __syncthreads();
    float* stage = reinterpret_cast<float*>(smh);
    #pragma unroll
    for (int i = 0; i < 4; i++)
        #pragma unroll
        for (int j = 0; j < 2; j++)
            wmma::store_matrix_sync(stage + (wm + i*16)*SP + wn + j*16,
                                    acc[i][j], SP, wmma::mem_row_major);
    __syncthreads();

    #pragma unroll
    for (int it = 0; it < 8; it++) {
        int idx = tid + 256*it;
        int r = idx >> 4;
        int c = (idx & 15) * 8;
        const float* srow = stage + r*SP + c;
        if (OUT_HALF) {
            __half* dst = Ch + (size_t)(bm + r) * N + bn + c;
            #pragma unroll
            for (int k = 0; k < 4; k++)
                *(__half2*)(dst + 2*k) = __floats2half2_rn(srow[2*k], srow[2*k+1]);
        } else {
            float* dst = Cf + (size_t)(bm + r) * N + bn + c;
            float4 v0 = *(const float4*)(srow);
            float4 v1 = *(const float4*)(srow + 4);
            if (WITH_BIAS) {
                const float* bp = bias + bn + c;
                v0.x += bp[0]; v0.y += bp[1]; v0.z += bp[2]; v0.w += bp[3];
                v1.x += bp[4]; v1.y += bp[5]; v1.z += bp[6]; v1.w += bp[7];
            }
            *(float4*)(dst)     = v0;
            *(float4*)(dst + 4) = v1;
        }
    }
}

// ---------------------------------------------------------------------------
// RoPE + L2 norm: fp16 in/out, in place (q pre-scaled by 1/8).
// ---------------------------------------------------------------------------
__global__ void __launch_bounds__(256) rope_norm_kernel(__half* __restrict__ qkvh)
{
    const int gw = (blockIdx.x * blockDim.x + threadIdx.x) >> 5;
    const int lane = threadIdx.x & 31;
    const int which = gw & 1;
    const int h = (gw >> 1) & (Hn - 1);
    const int t = (gw >> 5) & (Tn - 1);
    const int b = gw >> 16;

    __half* d = qkvh + (size_t)(b*Tn + t) * QKVN + which*Dn + h*HDn;

    const float inv_freq = exp2f(-(float)lane * (13.287712379549449f / 32.f));
    const float ang = (float)t * inv_freq;
    float s, c;
    sincosf(ang, &s, &c);

    const float x1 = __half2float(d[lane]);
    const float x2 = __half2float(d[lane + 32]);
    const float r1 = x1*c - x2*s;
    const float r2 = x1*s + x2*c;

    float ss = r1*r1 + r2*r2;
    #pragma unroll
    for (int off2 = 16; off2; off2 >>= 1)
        ss += __shfl_xor_sync(0xffffffffu, ss, off2);

    float inv = rsqrtf(ss + 1e-6f);
    if (which == 0) inv *= 0.125f;
    d[lane]      = __float2half(r1 * inv);
    d[lane + 32] = __float2half(r2 * inv);
}

// ---------------------------------------------------------------------------
// FP16 flash attention: 128 q-rows / 256 threads / 8 warps, half S
// accumulator, polynomial exp (|S|<=0.125), 3 blocks/SM.
// ---------------------------------------------------------------------------
#define APH 72
#define OXP 68
#define KV_STGH (64*APH)
#define SM_Q   0
#define SM_K   (SM_Q + 128*APH)
#define SM_V   (SM_K + 2*KV_STGH)
#define SM_P   (SM_V + 2*KV_STGH)
#define SM_HALVES (SM_P + 128*APH)
#define ATT_SMEM (SM_HALVES*2 + 128*4)

__global__ void __launch_bounds__(256) attn_h_kernel(
    const __half* __restrict__ qkvh, __half* __restrict__ outp)
{
    extern __shared__ __half smh[];
    __half* Qs = smh + SM_Q;
    __half* Ks = smh + SM_K;
    __half* Vs = smh + SM_V;
    __half* Ph = smh + SM_P;
    float* lrow = (float*)(smh + SM_HALVES);
    float* Ostage = (float*)(smh + SM_K);

    const int tid  = threadIdx.x;
    const int w    = tid >> 5;
    const int lane = tid & 31;

    const int qt = blockIdx.x & 15;
    const int h  = (blockIdx.x >> 4) & (Hn-1);
    const int b  = blockIdx.x >> 8;
    const int q0 = qt * 128;

    const __half* qbase = qkvh + (size_t)(b*Tn) * QKVN + h*HDn;
    const __half* kbase = qbase + Dn;
    const __half* vbase = qbase + 2*Dn;

    auto prefetch_kv = [&](int kt, int stg) {
        __half* kd = Ks + stg*KV_STGH;
        __half* vd = Vs + stg*KV_STGH;
        #pragma unroll
        for (int i = 0; i < 2; i++) {
            int id = tid + 256*i;
            int r = id >> 3, c = (id & 7) * 8;
            cp16(s2u(kd + r*APH + c), kbase + (size_t)(kt*64 + r) * QKVN + c);
        }
        #pragma unroll
        for (int i = 0; i < 2; i++) {
            int id = tid + 256*i;
            int r = id >> 3, c = (id & 7) * 8;
            cp16(s2u(vd + r*APH + c), vbase + (size_t)(kt*64 + r) * QKVN + c);
        }
        cp_commit();
    };

    #pragma unroll
    for (int i = 0; i < 4; i++) {
        int id = tid + 256*i;
        int r = id >> 3, c = (id & 7) * 8;
        cp16(s2u(Qs + r*APH + c), qbase + (size_t)(q0 + r) * QKVN + c);
    }
    cp_commit();
    prefetch_kv(0, 0);

    if (tid < 128) lrow[tid] = 0.f;

    wmma::fragment<wmma::accumulator, 16, 16, 16, float> oacc[4];
    #pragma unroll
    for (int j = 0; j < 4; j++) wmma::fill_fragment(oacc[j], 0.f);

    const int rowm = w * 16;
    int stg = 0;

    for (int kt = 0; kt < Tn/64; kt++) {
        cp_wait0();
        __syncthreads();
        if (kt + 1 < Tn/64) prefetch_kv(kt + 1, stg ^ 1);

        const __half* kc = Ks + stg*KV_STGH;
        const __half* vc = Vs + stg*KV_STGH;

        // S = Q @ K^T, half accumulator (safe: |S| <= 0.125)
        wmma::fragment<wmma::accumulator, 16, 16, 16, __half> sacc[4];
        #pragma unroll
        for (int j = 0; j < 4; j++) wmma::fill_fragment(sacc[j], __float2half(0.f));
        #pragma unroll
        for (int ks = 0; ks < 4; ks++) {
            wmma::fragment<wmma::matrix_a, 16, 16, 16, __half, wmma::row_major> aq;
            wmma::load_matrix_sync(aq, Qs + rowm*APH + ks*16, APH);
            #pragma unroll
            for (int j = 0; j < 4; j++) {
                wmma::fragment<wmma::matrix_b, 16, 16, 16, __half, wmma::col_major> bk;
                wmma::load_matrix_sync(bk, kc + j*16*APH + ks*16, APH);
                wmma::mma_sync(sacc[j], aq, bk, sacc[j]);
            }
        }
        #pragma unroll
        for (int j = 0; j < 4; j++)
            wmma::store_matrix_sync(Ph + rowm*APH + j*16, sacc[j], APH, wmma::mem_row_major);
        __syncwarp();

        // P = half(exp(S)) in place (polynomial exp); row sums of rounded P.
        {
            const int rr = rowm + (lane >> 1);
            const int cc = (lane & 1) * 32;
            __half* pr = Ph + rr*APH + cc;
            float sum = 0.f;
            #pragma unroll
            for (int j = 0; j < 32; j += 2) {
                __half2 sv = *(__half2*)(pr + j);
                float e0 = exp_small(__half2float(__low2half(sv)));
                float e1 = exp_small(__half2float(__high2half(sv)));
                __half2 hp = __floats2half2_rn(e0, e1);
                *(__half2*)(pr + j) = hp;
                sum += __half2float(__low2half(hp)) + __half2float(__high2half(hp));
            }
            sum += __shfl_xor_sync(0xffffffffu, sum, 1);
            if (!(lane & 1)) lrow[rr] += sum;
        }
        __syncwarp();

        // O += P @ V
        #pragma unroll
        for (int ks = 0; ks < 4; ks++) {
            wmma::fragment<wmma::matrix_a, 16, 16, 16, __half, wmma::row_major> ap;
            wmma::load_matrix_sync(ap, Ph + rowm*APH + ks*16, APH);
            #pragma unroll
            for (int j = 0; j < 4; j++) {
                wmma::fragment<wmma::matrix_b, 16, 16, 16, __half, wmma::row_major> bv;
                wmma::load_matrix_sync(bv, vc + ks*16*APH + j*16, APH);
                wmma::mma_sync(oacc[j], ap, bv, oacc[j]);
            }
        }
        stg ^= 1;
    }

    __syncthreads();
    #pragma unroll
    for (int j = 0; j < 4; j++)
        wmma::store_matrix_sync(Ostage + rowm*OXP + j*16, oacc[j], OXP, wmma::mem_row_major);
    __syncthreads();

    {
        const int r  = tid >> 1;
        const int c0 = (tid & 1) * 32;
        const float inv = 1.f / lrow[r];
        const float* srcr = Ostage + r*OXP + c0;
        __half* dst = outp + (size_t)(b*Tn + q0 + r) * Dn + h*HDn + c0;
        #pragma unroll
        for (int j = 0; j < 32; j += 2)
            *(__half2*)(dst + j) = __floats2half2_rn(srcr[j] * inv, srcr[j+1] * inv);
    }
}

// ---------------------------------------------------------------------------
extern "C" void kernel_launch(void* const* d_in, const int* in_sizes, int n_in,
                              void* d_out, int out_size)
{
    const float* x    = (const float*)d_in[0];
    const float* Wqkv = (const float*)d_in[1];
    const float* Wo   = (const float*)d_in[2];
    const float* bo   = (const float*)d_in[3];
    float* out = (float*)d_out;

    __half *qkvh, *atth, *xh, *wqh, *woh;
    cudaGetSymbolAddress((void**)&qkvh, g_qkvh);
    cudaGetSymbolAddress((void**)&atth, g_atth);
    cudaGetSymbolAddress((void**)&xh,   g_xh);
    cudaGetSymbolAddress((void**)&wqh,  g_wqh);
    cudaGetSymbolAddress((void**)&woh,  g_woh);

    cudaFuncSetAttribute((const void*)gemm_h<1,0>,
                         cudaFuncAttributeMaxDynamicSharedMemorySize, GEMM_SMEM);
    cudaFuncSetAttribute((const void*)gemm_h<0,1>,
                         cudaFuncAttributeMaxDynamicSharedMemorySize, GEMM_SMEM);
    cudaFuncSetAttribute(attn_h_kernel,
                         cudaFuncAttributeMaxDynamicSharedMemorySize, ATT_SMEM);

    // 0) fp16 conversions of inputs
    {
        int n4;
        n4 = MROWS*Dn/4;  f2h_kernel<<<(n4+255)/256, 256>>>(x,    xh,  n4);
        n4 = Dn*QKVN/4;   f2h_kernel<<<(n4+255)/256, 256>>>(Wqkv, wqh, n4);
        n4 = Dn*Dn/4;     f2h_kernel<<<(n4+255)/256, 256>>>(Wo,   woh, n4);
    }
    // 1) qkvh(fp16) = xh @ wqh
    {
        dim3 grid(QKVN/128, MROWS/128);
        gemm_h<1,0><<<grid, 256, GEMM_SMEM>>>(xh, wqh, nullptr, qkvh, nullptr,
                                              MROWS, QKVN, Dn);
    }
    // 2) RoPE + L2 norm in place (q prescaled)
    {
        int warps = Bn*Tn*Hn*2;
        rope_norm_kernel<<<warps/8, 256>>>(qkvh);
    }
    // 3) attention
    {
        dim3 grid(Bn * Hn * (Tn/128));   // 1024
        attn_h_kernel<<<grid, 256, ATT_SMEM>>>(qkvh, atth);
    }
    // 4) out(fp32) = atth @ woh + bo
    {
        dim3 grid(Dn/128, MROWS/128);
        gemm_h<0,1><<<grid, 256, GEMM_SMEM>>>(atth, woh, bo, nullptr, out,
                                              MROWS, Dn, Dn);
    }
}